// round 10
// baseline (speedup 1.0000x reference)
#include <cuda_runtime.h>
#include <cuda_bf16.h>
#include <cuda_fp16.h>
#include <stdint.h>

#define Nn 50000
#define Ee 800000
#define Qq 200000
#define Dd 256
#define RB 272          // fp8 row stride in SMEM bytes (17*16, odd -> conflict-free)

// ---------------- device scratch ----------------
__device__ uint4 g_h8v[Nn * 16];          // GEMM output h, fp8 e4m3, scale x16
__device__ uint4 g_x8v[Nn * 16];          // agg output x, fp8: layer0 scale x16, layer1 scale x8
__device__ float g_dinv[Nn];
__device__ int   g_deg[Nn];
__device__ int   g_ptr[Nn];
__device__ int   g_fill[Nn];
__device__ int   g_cursor;
__device__ int   g_ccol[Ee];
__device__ __half g_cnormh[Ee];
__device__ unsigned char g_W1q[Dd * Dd];  // [n][k] fp8, x16
__device__ unsigned char g_W2q[Dd * Dd];
__device__ unsigned char g_P1q[Dd * Dd];

// ---------------- helpers ----------------
__device__ __forceinline__ unsigned short pack_e2(float lo, float hi) {
    unsigned short r;
    asm("cvt.rn.satfinite.e4m3x2.f32 %0, %1, %2;" : "=h"(r) : "f"(hi), "f"(lo));
    return r;
}
__device__ __forceinline__ __half2 e2h(unsigned short s) {
    unsigned r;
    asm("cvt.rn.f16x2.e4m3x2 %0, %1;" : "=r"(r) : "h"(s));
    return *reinterpret_cast<__half2*>(&r);
}
__device__ __forceinline__ unsigned short h2e2(__half2 h) {
    unsigned short r;
    asm("cvt.rn.satfinite.e4m3x2.f16x2 %0, %1;" : "=h"(r) : "r"(*reinterpret_cast<unsigned*>(&h)));
    return r;
}
__device__ __forceinline__ unsigned s2u(const void* p) {
    return (unsigned)__cvta_generic_to_shared(p);
}
__device__ __forceinline__ void mma_e4m3(float* c, const unsigned* a, unsigned b0, unsigned b1) {
    asm volatile(
        "mma.sync.aligned.m16n8k32.row.col.f32.e4m3.e4m3.f32 "
        "{%0,%1,%2,%3}, {%4,%5,%6,%7}, {%8,%9}, {%0,%1,%2,%3};\n"
        : "+f"(c[0]), "+f"(c[1]), "+f"(c[2]), "+f"(c[3])
        : "r"(a[0]), "r"(a[1]), "r"(a[2]), "r"(a[3]), "r"(b0), "r"(b1));
}
#define LDSM4(R0,R1,R2,R3,ADDR) \
    asm volatile("ldmatrix.sync.aligned.m8n8.x4.shared.b16 {%0,%1,%2,%3}, [%4];" \
                 : "=r"(R0), "=r"(R1), "=r"(R2), "=r"(R3) : "r"(ADDR))

// ---------------- preprocessing ----------------
// zero deg/cursor + quantize weights to fp8 x16 (transposed [n][k])
__global__ void k_init(const float* __restrict__ W1, const float* __restrict__ W2,
                       const float* __restrict__ P1) {
    int idx = blockIdx.x * blockDim.x + threadIdx.x;
    if (idx < Nn) g_deg[idx] = 0;
    if (idx == 0) g_cursor = 0;
    if (idx < 3 * Dd * Dd / 2) {
        int m = idx >> 15;
        int p = idx & 32767;
        int n = p >> 7;
        int k = (p & 127) * 2;
        const float* src = (m == 0) ? W1 : ((m == 1) ? W2 : P1);
        unsigned char* dst = (m == 0) ? g_W1q : ((m == 1) ? g_W2q : g_P1q);
        float lo = src[k * Dd + n] * 16.f;
        float hi = src[(k + 1) * Dd + n] * 16.f;
        *reinterpret_cast<unsigned short*>(&dst[n * Dd + k]) = pack_e2(lo, hi);
    }
}
__global__ void k_hist(const int* __restrict__ row) {
    int e = blockIdx.x * blockDim.x + threadIdx.x;
    if (e < Ee) atomicAdd(&g_deg[row[e]], 1);
}
// order-free CSR segment allocation (no scan needed: segment order irrelevant)
__global__ void k_alloc() {
    int i = blockIdx.x * blockDim.x + threadIdx.x;
    if (i < Nn) {
        int d = g_deg[i];
        int pos = atomicAdd(&g_cursor, d);
        g_ptr[i]  = pos;
        g_fill[i] = pos;
        g_dinv[i] = rsqrtf((float)d + 1.0f);
    }
}
__global__ void k_fill(const int* __restrict__ row, const int* __restrict__ col) {
    int e = blockIdx.x * blockDim.x + threadIdx.x;
    if (e < Ee) {
        int r = row[e], c = col[e];
        int pos = atomicAdd(&g_fill[r], 1);
        g_ccol[pos]   = c;
        g_cnormh[pos] = __float2half(g_dinv[r] * g_dinv[c]);
    }
}

// ---------------- persistent fp8 GEMM: g_h8 = 16*(A @ W) --------------------------
// layer 0: A = emb (fp32) quantized x16 ; layer 1: A = g_x8v (fp8, x16)
__global__ void __launch_bounds__(256, 2) k_gemm(const float* __restrict__ Af, int layer) {
    extern __shared__ char smem[];
    unsigned char* Ws = reinterpret_cast<unsigned char*>(smem);  // [256][RB]
    unsigned char* As = Ws + Dd * RB;                            // [64][RB]

    const unsigned char* Wq = (layer == 0) ? g_W1q : g_W2q;
    int tid = threadIdx.x;

    // stage W once: 4096 uint4
    const uint4* wg = reinterpret_cast<const uint4*>(Wq);
    #pragma unroll
    for (int i = 0; i < 16; i++) {
        int idx = tid + i * 256;
        int n = idx >> 4, c16 = idx & 15;
        *reinterpret_cast<uint4*>(&Ws[n * RB + c16 * 16]) = wg[idx];
    }

    int w = tid >> 5, lane = tid & 31;
    int g = lane >> 2, t = lane & 3;
    int mw = (w & 1) * 32, nw = (w >> 1) * 64;

    int l4 = lane & 15, lh = lane >> 4;
    unsigned abase0 = s2u(&As[(mw + l4) * RB + lh * 16]);
    unsigned abase1 = abase0 + 16 * RB;
    unsigned bbase[4];
    #pragma unroll
    for (int p = 0; p < 4; p++) {
        int nr = nw + p * 16 + (lane >> 4) * 8 + (lane & 7);
        int kb = ((lane >> 3) & 1) * 16;
        bbase[p] = s2u(&Ws[nr * RB + kb]);
    }

    const int NT = (Nn + 63) / 64;
    for (int tile = blockIdx.x; tile < NT; tile += gridDim.x) {
        int mbase = tile * 64;
        __syncthreads();
        if (layer == 0) {
            // fp32 emb -> fp8 x16 ; 1024 out-uint4, 4 per thread
            const float4* a4 = reinterpret_cast<const float4*>(Af);
            #pragma unroll
            for (int i = 0; i < 4; i++) {
                int o = tid * 4 + i;
                int r = o >> 4, c16 = o & 15;
                int gr = mbase + r;
                uint4 u = make_uint4(0u, 0u, 0u, 0u);
                if (gr < Nn) {
                    unsigned short* us = reinterpret_cast<unsigned short*>(&u);
                    #pragma unroll
                    for (int j = 0; j < 4; j++) {
                        float4 f = a4[gr * 64 + c16 * 4 + j];
                        us[2 * j]     = pack_e2(f.x * 16.f, f.y * 16.f);
                        us[2 * j + 1] = pack_e2(f.z * 16.f, f.w * 16.f);
                    }
                }
                *reinterpret_cast<uint4*>(&As[r * RB + c16 * 16]) = u;
            }
        } else {
            // fp8 copy
            #pragma unroll
            for (int i = 0; i < 4; i++) {
                int o = tid * 4 + i;
                int r = o >> 4, c16 = o & 15;
                int gr = mbase + r;
                uint4 u = make_uint4(0u, 0u, 0u, 0u);
                if (gr < Nn) u = g_x8v[gr * 16 + c16];
                *reinterpret_cast<uint4*>(&As[r * RB + c16 * 16]) = u;
            }
        }
        __syncthreads();

        float acc[2][8][4];
        #pragma unroll
        for (int mt = 0; mt < 2; mt++)
            #pragma unroll
            for (int nt = 0; nt < 8; nt++)
                #pragma unroll
                for (int i = 0; i < 4; i++) acc[mt][nt][i] = 0.f;

        #pragma unroll
        for (int ks = 0; ks < 8; ks++) {
            unsigned off = ks * 32;   // 32 fp8 per k-step
            unsigned a0[4], a1[4];
            LDSM4(a0[0], a0[1], a0[2], a0[3], abase0 + off);
            LDSM4(a1[0], a1[1], a1[2], a1[3], abase1 + off);
            #pragma unroll
            for (int p = 0; p < 4; p++) {
                unsigned b0, b1, b2, b3;
                LDSM4(b0, b1, b2, b3, bbase[p] + off);
                mma_e4m3(acc[0][2 * p],     a0, b0, b1);
                mma_e4m3(acc[0][2 * p + 1], a0, b2, b3);
                mma_e4m3(acc[1][2 * p],     a1, b0, b1);
                mma_e4m3(acc[1][2 * p + 1], a1, b2, b3);
            }
        }

        // acc = 256*(A@W); h8 = 16*h = acc/16
        unsigned char* h8 = reinterpret_cast<unsigned char*>(g_h8v);
        const float S = 0.0625f;
        #pragma unroll
        for (int mt = 0; mt < 2; mt++) {
            int r0 = mbase + mw + mt * 16 + g;
            #pragma unroll
            for (int nt = 0; nt < 8; nt++) {
                int c = nw + nt * 8 + 2 * t;
                if (r0 < Nn)
                    *reinterpret_cast<unsigned short*>(&h8[r0 * Dd + c]) =
                        pack_e2(acc[mt][nt][0] * S, acc[mt][nt][1] * S);
                if (r0 + 8 < Nn)
                    *reinterpret_cast<unsigned short*>(&h8[(r0 + 8) * Dd + c]) =
                        pack_e2(acc[mt][nt][2] * S, acc[mt][nt][3] * S);
            }
        }
    }
}

// ---------------- CSR gather-aggregate (fp8 in, f16x2 accum, fp8 out) ----------------
// layer0: out = 16*relu(agg+b1) = relu(acc + 16 b1)  (acc = 16*agg)
// layer1: out =  8*(agg+b2)     = acc/2 + 8 b2
__global__ void __launch_bounds__(256) k_agg(const float* __restrict__ bias, int layer) {
    int wid  = (blockIdx.x * blockDim.x + threadIdx.x) >> 5;
    int lane = threadIdx.x & 31;
    if (wid >= Nn) return;

    const uint2* h2 = reinterpret_cast<const uint2*>(g_h8v);
    __half2 acc[4];
    {
        uint2 u = h2[wid * 32 + lane];
        float di = g_dinv[wid];
        __half2 n2 = __float2half2_rn(di * di);
        const unsigned short* us = reinterpret_cast<const unsigned short*>(&u);
        #pragma unroll
        for (int i = 0; i < 4; i++) acc[i] = __hmul2(n2, e2h(us[i]));
    }

    int s = g_ptr[wid];
    int e = s + g_deg[wid];
    int j = s;
    for (; j + 1 < e; j += 2) {
        int c0 = g_ccol[j], c1 = g_ccol[j + 1];
        __half2 n0 = __half2half2(g_cnormh[j]);
        __half2 n1 = __half2half2(g_cnormh[j + 1]);
        uint2 u0 = h2[c0 * 32 + lane];
        uint2 u1 = h2[c1 * 32 + lane];
        const unsigned short* s0 = reinterpret_cast<const unsigned short*>(&u0);
        const unsigned short* s1 = reinterpret_cast<const unsigned short*>(&u1);
        #pragma unroll
        for (int i = 0; i < 4; i++) acc[i] = __hfma2(n0, e2h(s0[i]), acc[i]);
        #pragma unroll
        for (int i = 0; i < 4; i++) acc[i] = __hfma2(n1, e2h(s1[i]), acc[i]);
    }
    if (j < e) {
        int c0 = g_ccol[j];
        __half2 n0 = __half2half2(g_cnormh[j]);
        uint2 u0 = h2[c0 * 32 + lane];
        const unsigned short* s0 = reinterpret_cast<const unsigned short*>(&u0);
        #pragma unroll
        for (int i = 0; i < 4; i++) acc[i] = __hfma2(n0, e2h(s0[i]), acc[i]);
    }

    float f[8];
    #pragma unroll
    for (int i = 0; i < 4; i++) {
        f[2 * i]     = __low2float(acc[i]);
        f[2 * i + 1] = __high2float(acc[i]);
    }
    const float4* b4 = reinterpret_cast<const float4*>(bias);
    float4 b0 = b4[lane * 2], b1 = b4[lane * 2 + 1];
    float bb[8] = {b0.x, b0.y, b0.z, b0.w, b1.x, b1.y, b1.z, b1.w};

    if (layer == 0) {
        #pragma unroll
        for (int i = 0; i < 8; i++) f[i] = fmaxf(f[i] + 16.f * bb[i], 0.f);
    } else {
        #pragma unroll
        for (int i = 0; i < 8; i++) f[i] = f[i] * 0.5f + 8.f * bb[i];
    }
    uint2 o;
    unsigned short* os = reinterpret_cast<unsigned short*>(&o);
    os[0] = pack_e2(f[0], f[1]);
    os[1] = pack_e2(f[2], f[3]);
    os[2] = pack_e2(f[4], f[5]);
    os[3] = pack_e2(f[6], f[7]);
    reinterpret_cast<uint2*>(g_x8v)[wid * 32 + lane] = o;
}

// -------- persistent fused link predictor (fp8 gather + fp8 MMA) ----------
__global__ void __launch_bounds__(256, 2) k_query(const int* __restrict__ e0,
                                                  const int* __restrict__ e1,
                                                  const float* __restrict__ P1b,
                                                  const float* __restrict__ P2w,
                                                  const float* __restrict__ P2b,
                                                  float* __restrict__ out) {
    extern __shared__ char smem[];
    unsigned char* Ws = reinterpret_cast<unsigned char*>(smem);  // P1q [256][RB]
    unsigned char* As = Ws + Dd * RB;                            // [64][RB]
    __shared__ float sb1[Dd];
    __shared__ float sp2[Dd];
    __shared__ float slog[64];

    int tid = threadIdx.x;
    const uint4* wg = reinterpret_cast<const uint4*>(g_P1q);
    #pragma unroll
    for (int i = 0; i < 16; i++) {
        int idx = tid + i * 256;
        int n = idx >> 4, c16 = idx & 15;
        *reinterpret_cast<uint4*>(&Ws[n * RB + c16 * 16]) = wg[idx];
    }
    sb1[tid] = P1b[tid];
    sp2[tid] = P2w[tid];
    float p2bias = P2b[0];

    int w = tid >> 5, lane = tid & 31;
    int g = lane >> 2, t = lane & 3;
    int mw = (w & 1) * 32, nw = (w >> 1) * 64;
    int r  = tid >> 2, tr = tid & 3;

    int l4 = lane & 15, lh = lane >> 4;
    unsigned abase0 = s2u(&As[(mw + l4) * RB + lh * 16]);
    unsigned abase1 = abase0 + 16 * RB;
    unsigned bbase[4];
    #pragma unroll
    for (int p = 0; p < 4; p++) {
        int nr = nw + p * 16 + (lane >> 4) * 8 + (lane & 7);
        int kb = ((lane >> 3) & 1) * 16;
        bbase[p] = s2u(&Ws[nr * RB + kb]);
    }

    const int NT = (Qq + 63) / 64;
    for (int tile = blockIdx.x; tile < NT; tile += gridDim.x) {
        __syncthreads();
        if (tid < 64) slog[tid] = 0.f;

        int q = tile * 64 + r;
        bool qv = (q < Qq);
        int i0 = 0, i1 = 0;
        if (qv) { i0 = e0[q]; i1 = e1[q]; }
        #pragma unroll
        for (int i = 0; i < 4; i++) {
            int ci = tr * 4 + i;
            uint4 ua = g_x8v[i0 * 16 + ci];
            uint4 ub = g_x8v[i1 * 16 + ci];
            uint4 o = make_uint4(0u, 0u, 0u, 0u);
            if (qv) {
                const unsigned short* pa = reinterpret_cast<const unsigned short*>(&ua);
                const unsigned short* pb = reinterpret_cast<const unsigned short*>(&ub);
                unsigned short* po = reinterpret_cast<unsigned short*>(&o);
                #pragma unroll
                for (int k = 0; k < 8; k++)
                    po[k] = h2e2(__hmul2(e2h(pa[k]), e2h(pb[k])));
            }
            *reinterpret_cast<uint4*>(&As[r * RB + ci * 16]) = o;
        }
        __syncthreads();

        float acc[2][8][4];
        #pragma unroll
        for (int mt = 0; mt < 2; mt++)
            #pragma unroll
            for (int nt = 0; nt < 8; nt++)
                #pragma unroll
                for (int i = 0; i < 4; i++) acc[mt][nt][i] = 0.f;

        #pragma unroll
        for (int ks = 0; ks < 8; ks++) {
            unsigned off = ks * 32;
            unsigned a0[4], a1[4];
            LDSM4(a0[0], a0[1], a0[2], a0[3], abase0 + off);
            LDSM4(a1[0], a1[1], a1[2], a1[3], abase1 + off);
            #pragma unroll
            for (int p = 0; p < 4; p++) {
                unsigned b0, b1, b2, b3;
                LDSM4(b0, b1, b2, b3, bbase[p] + off);
                mma_e4m3(acc[0][2 * p],     a0, b0, b1);
                mma_e4m3(acc[0][2 * p + 1], a0, b2, b3);
                mma_e4m3(acc[1][2 * p],     a1, b0, b1);
                mma_e4m3(acc[1][2 * p + 1], a1, b2, b3);
            }
        }

        // As = 64*prod, Ws = 16*P1 -> acc = 1024*(prod@P1)
        const float ISC = 1.f / 1024.f;
        #pragma unroll
        for (int mt = 0; mt < 2; mt++) {
            float s0 = 0.f, s1 = 0.f;
            #pragma unroll
            for (int nt = 0; nt < 8; nt++) {
                int c = nw + nt * 8 + 2 * t;
                float v;
                v = acc[mt][nt][0] * ISC + sb1[c];     v = fmaxf(v, 0.f); s0 = fmaf(v, sp2[c], s0);
                v = acc[mt][nt][1] * ISC + sb1[c + 1]; v = fmaxf(v, 0.f); s0 = fmaf(v, sp2[c + 1], s0);
                v = acc[mt][nt][2] * ISC + sb1[c];     v = fmaxf(v, 0.f); s1 = fmaf(v, sp2[c], s1);
                v = acc[mt][nt][3] * ISC + sb1[c + 1]; v = fmaxf(v, 0.f); s1 = fmaf(v, sp2[c + 1], s1);
            }
            s0 += __shfl_xor_sync(0xffffffffu, s0, 1);
            s0 += __shfl_xor_sync(0xffffffffu, s0, 2);
            s1 += __shfl_xor_sync(0xffffffffu, s1, 1);
            s1 += __shfl_xor_sync(0xffffffffu, s1, 2);
            if (t == 0) {
                atomicAdd(&slog[mw + mt * 16 + g],     s0);
                atomicAdd(&slog[mw + mt * 16 + g + 8], s1);
            }
        }
        __syncthreads();
        if (tid < 64) {
            int qo = tile * 64 + tid;
            if (qo < Qq) {
                float z = slog[tid] + p2bias;
                out[qo] = 1.0f / (1.0f + __expf(-z));
            }
        }
    }
}

// ---------------- launch ----------------
extern "C" void kernel_launch(void* const* d_in, const int* in_sizes, int n_in,
                              void* d_out, int out_size) {
    const int*   ei   = (const int*)d_in[0];
    const int*   qe   = (const int*)d_in[1];
    const float* emb  = (const float*)d_in[2];
    const float* W1   = (const float*)d_in[3];
    const float* b1   = (const float*)d_in[4];
    const float* W2   = (const float*)d_in[5];
    const float* b2   = (const float*)d_in[6];
    const float* P1w  = (const float*)d_in[7];
    const float* P1b  = (const float*)d_in[8];
    const float* P2w  = (const float*)d_in[9];
    const float* P2b  = (const float*)d_in[10];
    float* out = (float*)d_out;

    const int SMEM = (Dd + 64) * RB;  // 87040 bytes
    cudaFuncSetAttribute(k_gemm,  cudaFuncAttributeMaxDynamicSharedMemorySize, SMEM);
    cudaFuncSetAttribute(k_query, cudaFuncAttributeMaxDynamicSharedMemorySize, SMEM);

    k_init<<<(3 * Dd * Dd / 2 + 255) / 256, 256>>>(W1, W2, P1w);
    k_hist<<<(Ee + 255) / 256, 256>>>(ei);
    k_alloc<<<(Nn + 255) / 256, 256>>>();
    k_fill<<<(Ee + 255) / 256, 256>>>(ei, ei + Ee);

    k_gemm<<<296, 256, SMEM>>>(emb, 0);
    k_agg<<<(Nn * 32 + 255) / 256, 256>>>(b1, 0);
    k_gemm<<<296, 256, SMEM>>>(nullptr, 1);
    k_agg<<<(Nn * 32 + 255) / 256, 256>>>(b2, 1);
    k_query<<<296, 256, SMEM>>>(qe, qe + Qq, P1b, P2w, P2b, out);
}

// round 11
// speedup vs baseline: 1.0019x; 1.0019x over previous
#include <cuda_runtime.h>
#include <cuda_bf16.h>
#include <cuda_fp16.h>
#include <stdint.h>

#define Nn 50000
#define Ee 800000
#define Qq 200000
#define Dd 256
#define RB 272          // fp8 row stride in SMEM bytes (17*16, odd -> conflict-free)

// ---------------- device scratch ----------------
__device__ uint4 g_h8v[Nn * 16];          // GEMM output h, fp8 e4m3, scale x16
__device__ uint4 g_x8v[Nn * 16];          // agg output x, fp8: layer0 scale x16, layer1 scale x8
__device__ float g_dinv[Nn];
__device__ int   g_deg[Nn];
__device__ int   g_ptr[Nn];
__device__ int   g_fill[Nn];
__device__ int   g_cursor;
__device__ int   g_ccol[Ee];
__device__ __half g_cnormh[Ee];
__device__ unsigned char g_W1q[Dd * Dd];  // [n][k] fp8, x16
__device__ unsigned char g_W2q[Dd * Dd];
__device__ unsigned char g_P1q[Dd * Dd];

// ---------------- helpers ----------------
__device__ __forceinline__ unsigned short pack_e2(float lo, float hi) {
    unsigned short r;
    asm("cvt.rn.satfinite.e4m3x2.f32 %0, %1, %2;" : "=h"(r) : "f"(hi), "f"(lo));
    return r;
}
__device__ __forceinline__ __half2 e2h(unsigned short s) {
    unsigned r;
    asm("cvt.rn.f16x2.e4m3x2 %0, %1;" : "=r"(r) : "h"(s));
    return *reinterpret_cast<__half2*>(&r);
}
__device__ __forceinline__ unsigned short h2e2(__half2 h) {
    unsigned short r;
    asm("cvt.rn.satfinite.e4m3x2.f16x2 %0, %1;" : "=h"(r) : "r"(*reinterpret_cast<unsigned*>(&h)));
    return r;
}
__device__ __forceinline__ unsigned s2u(const void* p) {
    return (unsigned)__cvta_generic_to_shared(p);
}
__device__ __forceinline__ void mma_e4m3(float* c, const unsigned* a, unsigned b0, unsigned b1) {
    asm volatile(
        "mma.sync.aligned.m16n8k32.row.col.f32.e4m3.e4m3.f32 "
        "{%0,%1,%2,%3}, {%4,%5,%6,%7}, {%8,%9}, {%0,%1,%2,%3};\n"
        : "+f"(c[0]), "+f"(c[1]), "+f"(c[2]), "+f"(c[3])
        : "r"(a[0]), "r"(a[1]), "r"(a[2]), "r"(a[3]), "r"(b0), "r"(b1));
}
#define LDSM4(R0,R1,R2,R3,ADDR) \
    asm volatile("ldmatrix.sync.aligned.m8n8.x4.shared.b16 {%0,%1,%2,%3}, [%4];" \
                 : "=r"(R0), "=r"(R1), "=r"(R2), "=r"(R3) : "r"(ADDR))

// ---------------- preprocessing ----------------
// zero deg/cursor + quantize weights to fp8 x16 (transposed [n][k])
__global__ void k_init(const float* __restrict__ W1, const float* __restrict__ W2,
                       const float* __restrict__ P1) {
    int idx = blockIdx.x * blockDim.x + threadIdx.x;
    if (idx < Nn) g_deg[idx] = 0;
    if (idx == 0) g_cursor = 0;
    if (idx < 3 * Dd * Dd / 2) {
        int m = idx >> 15;
        int p = idx & 32767;
        int n = p >> 7;
        int k = (p & 127) * 2;
        const float* src = (m == 0) ? W1 : ((m == 1) ? W2 : P1);
        unsigned char* dst = (m == 0) ? g_W1q : ((m == 1) ? g_W2q : g_P1q);
        float lo = src[k * Dd + n] * 16.f;
        float hi = src[(k + 1) * Dd + n] * 16.f;
        *reinterpret_cast<unsigned short*>(&dst[n * Dd + k]) = pack_e2(lo, hi);
    }
}
__global__ void k_hist(const int* __restrict__ row) {
    int e = blockIdx.x * blockDim.x + threadIdx.x;
    if (e < Ee) atomicAdd(&g_deg[row[e]], 1);
}
// order-free CSR segment allocation (no scan needed: segment order irrelevant)
__global__ void k_alloc() {
    int i = blockIdx.x * blockDim.x + threadIdx.x;
    if (i < Nn) {
        int d = g_deg[i];
        int pos = atomicAdd(&g_cursor, d);
        g_ptr[i]  = pos;
        g_fill[i] = pos;
        g_dinv[i] = rsqrtf((float)d + 1.0f);
    }
}
__global__ void k_fill(const int* __restrict__ row, const int* __restrict__ col) {
    int e = blockIdx.x * blockDim.x + threadIdx.x;
    if (e < Ee) {
        int r = row[e], c = col[e];
        int pos = atomicAdd(&g_fill[r], 1);
        g_ccol[pos]   = c;
        g_cnormh[pos] = __float2half(g_dinv[r] * g_dinv[c]);
    }
}

// ---------------- persistent fp8 GEMM: g_h8 = 16*(A @ W) --------------------------
// layer 0: A = emb (fp32) quantized x16 ; layer 1: A = g_x8v (fp8, x16)
__global__ void __launch_bounds__(256, 2) k_gemm(const float* __restrict__ Af, int layer) {
    extern __shared__ char smem[];
    unsigned char* Ws = reinterpret_cast<unsigned char*>(smem);  // [256][RB]
    unsigned char* As = Ws + Dd * RB;                            // [64][RB]

    const unsigned char* Wq = (layer == 0) ? g_W1q : g_W2q;
    int tid = threadIdx.x;

    // stage W once: 4096 uint4
    const uint4* wg = reinterpret_cast<const uint4*>(Wq);
    #pragma unroll
    for (int i = 0; i < 16; i++) {
        int idx = tid + i * 256;
        int n = idx >> 4, c16 = idx & 15;
        *reinterpret_cast<uint4*>(&Ws[n * RB + c16 * 16]) = wg[idx];
    }

    int w = tid >> 5, lane = tid & 31;
    int g = lane >> 2, t = lane & 3;
    int mw = (w & 1) * 32, nw = (w >> 1) * 64;

    int l4 = lane & 15, lh = lane >> 4;
    unsigned abase0 = s2u(&As[(mw + l4) * RB + lh * 16]);
    unsigned abase1 = abase0 + 16 * RB;
    unsigned bbase[4];
    #pragma unroll
    for (int p = 0; p < 4; p++) {
        int nr = nw + p * 16 + (lane >> 4) * 8 + (lane & 7);
        int kb = ((lane >> 3) & 1) * 16;
        bbase[p] = s2u(&Ws[nr * RB + kb]);
    }

    const int NT = (Nn + 63) / 64;
    for (int tile = blockIdx.x; tile < NT; tile += gridDim.x) {
        int mbase = tile * 64;
        __syncthreads();
        if (layer == 0) {
            // fp32 emb -> fp8 x16 ; 1024 out-uint4, 4 per thread
            const float4* a4 = reinterpret_cast<const float4*>(Af);
            #pragma unroll
            for (int i = 0; i < 4; i++) {
                int o = tid * 4 + i;
                int r = o >> 4, c16 = o & 15;
                int gr = mbase + r;
                uint4 u = make_uint4(0u, 0u, 0u, 0u);
                if (gr < Nn) {
                    unsigned short* us = reinterpret_cast<unsigned short*>(&u);
                    #pragma unroll
                    for (int j = 0; j < 4; j++) {
                        float4 f = a4[gr * 64 + c16 * 4 + j];
                        us[2 * j]     = pack_e2(f.x * 16.f, f.y * 16.f);
                        us[2 * j + 1] = pack_e2(f.z * 16.f, f.w * 16.f);
                    }
                }
                *reinterpret_cast<uint4*>(&As[r * RB + c16 * 16]) = u;
            }
        } else {
            // fp8 copy
            #pragma unroll
            for (int i = 0; i < 4; i++) {
                int o = tid * 4 + i;
                int r = o >> 4, c16 = o & 15;
                int gr = mbase + r;
                uint4 u = make_uint4(0u, 0u, 0u, 0u);
                if (gr < Nn) u = g_x8v[gr * 16 + c16];
                *reinterpret_cast<uint4*>(&As[r * RB + c16 * 16]) = u;
            }
        }
        __syncthreads();

        float acc[2][8][4];
        #pragma unroll
        for (int mt = 0; mt < 2; mt++)
            #pragma unroll
            for (int nt = 0; nt < 8; nt++)
                #pragma unroll
                for (int i = 0; i < 4; i++) acc[mt][nt][i] = 0.f;

        #pragma unroll
        for (int ks = 0; ks < 8; ks++) {
            unsigned off = ks * 32;   // 32 fp8 per k-step
            unsigned a0[4], a1[4];
            LDSM4(a0[0], a0[1], a0[2], a0[3], abase0 + off);
            LDSM4(a1[0], a1[1], a1[2], a1[3], abase1 + off);
            #pragma unroll
            for (int p = 0; p < 4; p++) {
                unsigned b0, b1, b2, b3;
                LDSM4(b0, b1, b2, b3, bbase[p] + off);
                mma_e4m3(acc[0][2 * p],     a0, b0, b1);
                mma_e4m3(acc[0][2 * p + 1], a0, b2, b3);
                mma_e4m3(acc[1][2 * p],     a1, b0, b1);
                mma_e4m3(acc[1][2 * p + 1], a1, b2, b3);
            }
        }

        // acc = 256*(A@W); h8 = 16*h = acc/16
        unsigned char* h8 = reinterpret_cast<unsigned char*>(g_h8v);
        const float S = 0.0625f;
        #pragma unroll
        for (int mt = 0; mt < 2; mt++) {
            int r0 = mbase + mw + mt * 16 + g;
            #pragma unroll
            for (int nt = 0; nt < 8; nt++) {
                int c = nw + nt * 8 + 2 * t;
                if (r0 < Nn)
                    *reinterpret_cast<unsigned short*>(&h8[r0 * Dd + c]) =
                        pack_e2(acc[mt][nt][0] * S, acc[mt][nt][1] * S);
                if (r0 + 8 < Nn)
                    *reinterpret_cast<unsigned short*>(&h8[(r0 + 8) * Dd + c]) =
                        pack_e2(acc[mt][nt][2] * S, acc[mt][nt][3] * S);
            }
        }
    }
}

// ---------------- CSR gather-aggregate (fp8 in, f16x2 accum, fp8 out) ----------------
// layer0: out = 16*relu(agg+b1) = relu(acc + 16 b1)  (acc = 16*agg)
// layer1: out =  8*(agg+b2)     = acc/2 + 8 b2
__global__ void __launch_bounds__(256) k_agg(const float* __restrict__ bias, int layer) {
    int wid  = (blockIdx.x * blockDim.x + threadIdx.x) >> 5;
    int lane = threadIdx.x & 31;
    if (wid >= Nn) return;

    const uint2* h2 = reinterpret_cast<const uint2*>(g_h8v);
    __half2 acc[4];
    {
        uint2 u = h2[wid * 32 + lane];
        float di = g_dinv[wid];
        __half2 n2 = __float2half2_rn(di * di);
        const unsigned short* us = reinterpret_cast<const unsigned short*>(&u);
        #pragma unroll
        for (int i = 0; i < 4; i++) acc[i] = __hmul2(n2, e2h(us[i]));
    }

    int s = g_ptr[wid];
    int e = s + g_deg[wid];
    int j = s;
    for (; j + 1 < e; j += 2) {
        int c0 = g_ccol[j], c1 = g_ccol[j + 1];
        __half2 n0 = __half2half2(g_cnormh[j]);
        __half2 n1 = __half2half2(g_cnormh[j + 1]);
        uint2 u0 = h2[c0 * 32 + lane];
        uint2 u1 = h2[c1 * 32 + lane];
        const unsigned short* s0 = reinterpret_cast<const unsigned short*>(&u0);
        const unsigned short* s1 = reinterpret_cast<const unsigned short*>(&u1);
        #pragma unroll
        for (int i = 0; i < 4; i++) acc[i] = __hfma2(n0, e2h(s0[i]), acc[i]);
        #pragma unroll
        for (int i = 0; i < 4; i++) acc[i] = __hfma2(n1, e2h(s1[i]), acc[i]);
    }
    if (j < e) {
        int c0 = g_ccol[j];
        __half2 n0 = __half2half2(g_cnormh[j]);
        uint2 u0 = h2[c0 * 32 + lane];
        const unsigned short* s0 = reinterpret_cast<const unsigned short*>(&u0);
        #pragma unroll
        for (int i = 0; i < 4; i++) acc[i] = __hfma2(n0, e2h(s0[i]), acc[i]);
    }

    float f[8];
    #pragma unroll
    for (int i = 0; i < 4; i++) {
        f[2 * i]     = __low2float(acc[i]);
        f[2 * i + 1] = __high2float(acc[i]);
    }
    const float4* b4 = reinterpret_cast<const float4*>(bias);
    float4 b0 = b4[lane * 2], b1 = b4[lane * 2 + 1];
    float bb[8] = {b0.x, b0.y, b0.z, b0.w, b1.x, b1.y, b1.z, b1.w};

    if (layer == 0) {
        #pragma unroll
        for (int i = 0; i < 8; i++) f[i] = fmaxf(f[i] + 16.f * bb[i], 0.f);
    } else {
        #pragma unroll
        for (int i = 0; i < 8; i++) f[i] = f[i] * 0.5f + 8.f * bb[i];
    }
    uint2 o;
    unsigned short* os = reinterpret_cast<unsigned short*>(&o);
    os[0] = pack_e2(f[0], f[1]);
    os[1] = pack_e2(f[2], f[3]);
    os[2] = pack_e2(f[4], f[5]);
    os[3] = pack_e2(f[6], f[7]);
    reinterpret_cast<uint2*>(g_x8v)[wid * 32 + lane] = o;
}

// -------- persistent fused link predictor (fp8 gather + fp8 MMA) ----------
__global__ void __launch_bounds__(256, 2) k_query(const int* __restrict__ e0,
                                                  const int* __restrict__ e1,
                                                  const float* __restrict__ P1b,
                                                  const float* __restrict__ P2w,
                                                  const float* __restrict__ P2b,
                                                  float* __restrict__ out) {
    extern __shared__ char smem[];
    unsigned char* Ws = reinterpret_cast<unsigned char*>(smem);  // P1q [256][RB]
    unsigned char* As = Ws + Dd * RB;                            // [64][RB]
    __shared__ float sb1[Dd];
    __shared__ float sp2[Dd];
    __shared__ float slog[64];

    int tid = threadIdx.x;
    const uint4* wg = reinterpret_cast<const uint4*>(g_P1q);
    #pragma unroll
    for (int i = 0; i < 16; i++) {
        int idx = tid + i * 256;
        int n = idx >> 4, c16 = idx & 15;
        *reinterpret_cast<uint4*>(&Ws[n * RB + c16 * 16]) = wg[idx];
    }
    sb1[tid] = P1b[tid];
    sp2[tid] = P2w[tid];
    float p2bias = P2b[0];

    int w = tid >> 5, lane = tid & 31;
    int g = lane >> 2, t = lane & 3;
    int mw = (w & 1) * 32, nw = (w >> 1) * 64;
    int r  = tid >> 2, tr = tid & 3;

    int l4 = lane & 15, lh = lane >> 4;
    unsigned abase0 = s2u(&As[(mw + l4) * RB + lh * 16]);
    unsigned abase1 = abase0 + 16 * RB;
    unsigned bbase[4];
    #pragma unroll
    for (int p = 0; p < 4; p++) {
        int nr = nw + p * 16 + (lane >> 4) * 8 + (lane & 7);
        int kb = ((lane >> 3) & 1) * 16;
        bbase[p] = s2u(&Ws[nr * RB + kb]);
    }

    const int NT = (Qq + 63) / 64;
    for (int tile = blockIdx.x; tile < NT; tile += gridDim.x) {
        __syncthreads();
        if (tid < 64) slog[tid] = 0.f;

        int q = tile * 64 + r;
        bool qv = (q < Qq);
        int i0 = 0, i1 = 0;
        if (qv) { i0 = e0[q]; i1 = e1[q]; }
        #pragma unroll
        for (int i = 0; i < 4; i++) {
            int ci = tr * 4 + i;
            uint4 ua = g_x8v[i0 * 16 + ci];
            uint4 ub = g_x8v[i1 * 16 + ci];
            uint4 o = make_uint4(0u, 0u, 0u, 0u);
            if (qv) {
                const unsigned short* pa = reinterpret_cast<const unsigned short*>(&ua);
                const unsigned short* pb = reinterpret_cast<const unsigned short*>(&ub);
                unsigned short* po = reinterpret_cast<unsigned short*>(&o);
                #pragma unroll
                for (int k = 0; k < 8; k++)
                    po[k] = h2e2(__hmul2(e2h(pa[k]), e2h(pb[k])));
            }
            *reinterpret_cast<uint4*>(&As[r * RB + ci * 16]) = o;
        }
        __syncthreads();

        float acc[2][8][4];
        #pragma unroll
        for (int mt = 0; mt < 2; mt++)
            #pragma unroll
            for (int nt = 0; nt < 8; nt++)
                #pragma unroll
                for (int i = 0; i < 4; i++) acc[mt][nt][i] = 0.f;

        #pragma unroll
        for (int ks = 0; ks < 8; ks++) {
            unsigned off = ks * 32;
            unsigned a0[4], a1[4];
            LDSM4(a0[0], a0[1], a0[2], a0[3], abase0 + off);
            LDSM4(a1[0], a1[1], a1[2], a1[3], abase1 + off);
            #pragma unroll
            for (int p = 0; p < 4; p++) {
                unsigned b0, b1, b2, b3;
                LDSM4(b0, b1, b2, b3, bbase[p] + off);
                mma_e4m3(acc[0][2 * p],     a0, b0, b1);
                mma_e4m3(acc[0][2 * p + 1], a0, b2, b3);
                mma_e4m3(acc[1][2 * p],     a1, b0, b1);
                mma_e4m3(acc[1][2 * p + 1], a1, b2, b3);
            }
        }

        // As = 64*prod, Ws = 16*P1 -> acc = 1024*(prod@P1)
        const float ISC = 1.f / 1024.f;
        #pragma unroll
        for (int mt = 0; mt < 2; mt++) {
            float s0 = 0.f, s1 = 0.f;
            #pragma unroll
            for (int nt = 0; nt < 8; nt++) {
                int c = nw + nt * 8 + 2 * t;
                float v;
                v = acc[mt][nt][0] * ISC + sb1[c];     v = fmaxf(v, 0.f); s0 = fmaf(v, sp2[c], s0);
                v = acc[mt][nt][1] * ISC + sb1[c + 1]; v = fmaxf(v, 0.f); s0 = fmaf(v, sp2[c + 1], s0);
                v = acc[mt][nt][2] * ISC + sb1[c];     v = fmaxf(v, 0.f); s1 = fmaf(v, sp2[c], s1);
                v = acc[mt][nt][3] * ISC + sb1[c + 1]; v = fmaxf(v, 0.f); s1 = fmaf(v, sp2[c + 1], s1);
            }
            s0 += __shfl_xor_sync(0xffffffffu, s0, 1);
            s0 += __shfl_xor_sync(0xffffffffu, s0, 2);
            s1 += __shfl_xor_sync(0xffffffffu, s1, 1);
            s1 += __shfl_xor_sync(0xffffffffu, s1, 2);
            if (t == 0) {
                atomicAdd(&slog[mw + mt * 16 + g],     s0);
                atomicAdd(&slog[mw + mt * 16 + g + 8], s1);
            }
        }
        __syncthreads();
        if (tid < 64) {
            int qo = tile * 64 + tid;
            if (qo < Qq) {
                float z = slog[tid] + p2bias;
                out[qo] = 1.0f / (1.0f + __expf(-z));
            }
        }
    }
}

// ---------------- launch ----------------
extern "C" void kernel_launch(void* const* d_in, const int* in_sizes, int n_in,
                              void* d_out, int out_size) {
    const int*   ei   = (const int*)d_in[0];
    const int*   qe   = (const int*)d_in[1];
    const float* emb  = (const float*)d_in[2];
    const float* W1   = (const float*)d_in[3];
    const float* b1   = (const float*)d_in[4];
    const float* W2   = (const float*)d_in[5];
    const float* b2   = (const float*)d_in[6];
    const float* P1w  = (const float*)d_in[7];
    const float* P1b  = (const float*)d_in[8];
    const float* P2w  = (const float*)d_in[9];
    const float* P2b  = (const float*)d_in[10];
    float* out = (float*)d_out;

    const int SMEM = (Dd + 64) * RB;  // 87040 bytes
    cudaFuncSetAttribute(k_gemm,  cudaFuncAttributeMaxDynamicSharedMemorySize, SMEM);
    cudaFuncSetAttribute(k_query, cudaFuncAttributeMaxDynamicSharedMemorySize, SMEM);

    k_init<<<(3 * Dd * Dd / 2 + 255) / 256, 256>>>(W1, W2, P1w);
    k_hist<<<(Ee + 255) / 256, 256>>>(ei);
    k_alloc<<<(Nn + 255) / 256, 256>>>();
    k_fill<<<(Ee + 255) / 256, 256>>>(ei, ei + Ee);

    k_gemm<<<296, 256, SMEM>>>(emb, 0);
    k_agg<<<(Nn * 32 + 255) / 256, 256>>>(b1, 0);
    k_gemm<<<296, 256, SMEM>>>(nullptr, 1);
    k_agg<<<(Nn * 32 + 255) / 256, 256>>>(b2, 1);
    k_query<<<296, 256, SMEM>>>(qe, qe + Qq, P1b, P2w, P2b, out);
}